// round 16
// baseline (speedup 1.0000x reference)
#include <cuda_runtime.h>

#define NN   4096
#define TT   300
#define TW   10
#define NBLK 128
#define NT2  512
#define TJOIN 96            // step at which xgemm warps join the gather

// ---------------- device scratch ----------------
__device__ unsigned g_mask[NN * TW];
__device__ float    g_Xpart[4ull * 320 * NN];
__device__ __align__(256) unsigned long long g_slot[TT][NBLK];  // {tag=t+1, mask}
__device__ unsigned g_cnt;                                       // cumulative publishes
__device__ unsigned g_wcnt[TW];                                  // per-word tile counters

__device__ __forceinline__ void ldcgv2(const unsigned long long* p,
                                       unsigned long long& a, unsigned long long& b) {
    asm volatile("ld.global.cg.v2.u64 {%0,%1}, [%2];" : "=l"(a), "=l"(b) : "l"(p));
}
__device__ __forceinline__ void stcg64(unsigned long long* p, unsigned long long v) {
    asm volatile("st.global.cg.b64 [%0], %1;" :: "l"(p), "l"(v));
}
__device__ __forceinline__ unsigned ldcg32(const unsigned* p) {
    unsigned v; asm volatile("ld.global.cg.b32 %0, [%1];" : "=r"(v) : "l"(p)); return v;
}
__device__ __forceinline__ unsigned ldacq32(const unsigned* p) {
    unsigned v; asm volatile("ld.acquire.gpu.global.u32 %0, [%1];" : "=r"(v) : "l"(p)); return v;
}
__device__ __forceinline__ void red_release_add(unsigned* p, unsigned v) {
    asm volatile("red.release.gpu.global.add.u32 [%0], %1;" :: "l"(p), "r"(v) : "memory");
}
__device__ __forceinline__ float4 ldnc128(const float* p) {
    float4 v;
    asm volatile("ld.global.nc.v4.f32 {%0,%1,%2,%3}, [%4];"
                 : "=f"(v.x), "=f"(v.y), "=f"(v.z), "=f"(v.w) : "l"(p));
    return v;
}

#define BAR1(cnt)  asm volatile("bar.sync 1, %0;" :: "r"(cnt) : "memory")
#define BAR_GEMM() asm volatile("bar.sync 2, 256;" ::: "memory")

// ---------------- kernel 1: pack inp bits + clear sync state ----------------
__global__ void __launch_bounds__(256) pack_kernel(const int* __restrict__ inp) {
    const int blk  = blockIdx.x;
    const int word = blk % TW;
    const int i    = (blk / TW) * 256 + threadIdx.x;
    unsigned m = 0u;
    const int tb = word * 32;
    #pragma unroll
    for (int b = 0; b < 32; ++b) {
        int t = tb + b;
        if (t < TT) m |= (((unsigned)inp[(size_t)t * NN + i]) & 1u) << b;
    }
    g_mask[i * TW + word] = m;
    int gid = blk * 256 + threadIdx.x;
    if (gid < TT * NBLK) ((unsigned long long*)g_slot)[gid] = 0ull;
    if (gid == 0) g_cnt = 0u;
    if (gid < TW) g_wcnt[gid] = 0u;
}

// ---------------- shared gather routine (nw = 8 or 16 warps) ----------------
__device__ __forceinline__ float4 gather_rows(const float* wr, const int* sh_idx,
                                              int S, int myrow, int nw) {
    float4 acc = make_float4(0.f, 0.f, 0.f, 0.f);
    const int ustr = nw << 2;          // rows per wave
    const int istr = nw << 5;          // rows per 8-wave batch
    for (int base = 0; base < S; base += istr) {
        float4 rv[8];
        #pragma unroll
        for (int u = 0; u < 8; ++u) {
            int kk = base + u * ustr + myrow;
            float4 z = make_float4(0.f, 0.f, 0.f, 0.f);
            if (kk < S) z = ldnc128(wr + sh_idx[kk]);
            rv[u] = z;
        }
        #pragma unroll
        for (int u = 0; u < 8; ++u) {
            acc.x += rv[u].x; acc.y += rv[u].y;
            acc.z += rv[u].z; acc.w += rv[u].w;
        }
    }
    acc.x += __shfl_down_sync(0xffffffffu, acc.x, 16);
    acc.y += __shfl_down_sync(0xffffffffu, acc.y, 16);
    acc.z += __shfl_down_sync(0xffffffffu, acc.z, 16);
    acc.w += __shfl_down_sync(0xffffffffu, acc.w, 16);
    acc.x += __shfl_down_sync(0xffffffffu, acc.x, 8);
    acc.y += __shfl_down_sync(0xffffffffu, acc.y, 8);
    acc.z += __shfl_down_sync(0xffffffffu, acc.z, 8);
    acc.w += __shfl_down_sync(0xffffffffu, acc.w, 8);
    return acc;
}

// ---------------- kernel 2: fused persistent LIF + background X-GEMM ----------
// Warps 0-7: LIF pipeline. Warps 8-15: X-GEMM tiles, then JOIN the gather at
// t = TJOIN (barrier 1 switches 256 -> 512 threads at that fixed step).
__global__ void __launch_bounds__(NT2, 1)
lif_kernel(const float* __restrict__ w, const float* __restrict__ w_rec,
           float* __restrict__ out) {
    __shared__ unsigned long long Adup[128][18];   // xgemm warps only
    __shared__ unsigned sh_mask[128];
    __shared__ int      sh_off[128];
    __shared__ int      sh_total;
    __shared__ int      sh_idx[NN];
    __shared__ float4   part4[16][9];

    const int tid = threadIdx.x;
    const int bid = blockIdx.x;
    const int l   = tid & 31;
    const int wp  = tid >> 5;
    const int sub = l >> 3;
    const int ln8 = l & 7;
    const int j0  = bid * 32;

    // ================= warps 8-15: background X-GEMM, then join gather ========
    if (wp >= 8) {
        const int tid2 = tid - 256;
        for (int r = 0; r < 5; ++r) {
            const int tile = bid + (r << 7);       // word-ascending
            const int word = tile >> 6;
            const int s    = tile & 63;
            const int cc   = s >> 2;
            const int q    = s & 3;
            const int j    = cc * 256 + tid2;
            const int ibase = q * 1024;

            unsigned long long acc[16];
            #pragma unroll
            for (int k = 0; k < 16; ++k) acc[k] = 0ull;

            for (int sb = 0; sb < 8; ++sb) {
                int ib = ibase + sb * 128;
                BAR_GEMM();
                for (int e = tid2; e < 2048; e += 256) {
                    int ii = e >> 4, tp = e & 15;
                    unsigned m  = g_mask[(ib + ii) * TW + word];
                    unsigned lo = (m >> (2 * tp))     & 1u ? 0x3f800000u : 0u;
                    unsigned hi = (m >> (2 * tp + 1)) & 1u ? 0x3f800000u : 0u;
                    Adup[ii][tp] = ((unsigned long long)hi << 32) | lo;
                }
                BAR_GEMM();
                for (int ii = 0; ii < 128; ++ii) {
                    unsigned wu = __float_as_uint(w[(size_t)(ib + ii) * NN + j]);
                    unsigned long long wpk;
                    asm("mov.b64 %0, {%1, %1};" : "=l"(wpk) : "r"(wu));
                    const ulonglong2* ap = (const ulonglong2*)(&Adup[ii][0]);
                    #pragma unroll
                    for (int k = 0; k < 8; ++k) {
                        ulonglong2 a2 = ap[k];
                        asm("fma.rn.f32x2 %0, %1, %2, %0;" : "+l"(acc[2*k])   : "l"(wpk), "l"(a2.x));
                        asm("fma.rn.f32x2 %0, %1, %2, %0;" : "+l"(acc[2*k+1]) : "l"(wpk), "l"(a2.y));
                    }
                }
            }
            #pragma unroll
            for (int tp = 0; tp < 16; ++tp) {
                int t0 = word * 32 + 2 * tp;
                g_Xpart[((size_t)q * 320 + t0)     * NN + j] = __uint_as_float((unsigned)acc[tp]);
                g_Xpart[((size_t)q * 320 + t0 + 1) * NN + j] = __uint_as_float((unsigned)(acc[tp] >> 32));
            }
            __threadfence();
            BAR_GEMM();
            if (tid2 == 0) red_release_add(&g_wcnt[word], 1u);
        }
        // ---- join the gather from t = TJOIN onward ----
        const float* wr = w_rec + j0 + (ln8 << 2);
        const int myrow = (wp << 2) + sub;     // 32..63
        for (int t = TJOIN; t < TT; ++t) {
            BAR1(512);   // S1a
            BAR1(512);   // S1b: sh_idx + sh_total now valid
            float4 acc = gather_rows(wr, sh_idx, sh_total, myrow, 16);
            if (l < 8) part4[wp][ln8] = acc;
            BAR1(512);   // S2
        }
        return;
    }

    // ================= warps 0-7: LIF pipeline ==========
    // zero part4 rows 8-15 (read as exact zeros until the join)
    if (l < 8) part4[wp + 8][ln8] = make_float4(0.f, 0.f, 0.f, 0.f);
    if (tid == 0) sh_total = 0;
    BAR1(256);

    float v = 0.f, rt = 0.f, tl = 1.f;
    const float DECAY = 0.99004983374916805f;   // fp32(exp(-1/100))

    for (int t = 0; t < TT; ++t) {
        const int bc = (t >= TJOIN) ? 512 : 256;
        const int nw = (t >= TJOIN) ? 16 : 8;
        float x0 = 0.f, x1 = 0.f, x2 = 0.f, x3 = 0.f;
        if (wp == 0) {
            if ((t & 31) == 0) {               // wait for this word's Xpart tiles
                if (l == 0) {
                    while (ldacq32(&g_wcnt[t >> 5]) < 64u) {}
                }
                __syncwarp();
            }
            const int j = j0 + l;
            x0 = g_Xpart[(size_t)(0 * 320 + t) * NN + j];
            x1 = g_Xpart[(size_t)(1 * 320 + t) * NN + j];
            x2 = g_Xpart[(size_t)(2 * 320 + t) * NN + j];
            x3 = g_Xpart[(size_t)(3 * 320 + t) * NN + j];
            if (t > 0) {
                if (l == 0) {                  // poll ONE counter word
                    const unsigned want = 128u * (unsigned)t;
                    while (ldcg32(&g_cnt) < want) {}
                }
                __syncwarp();
                const unsigned long long* slot = &g_slot[t - 1][4 * l];
                const unsigned want = (unsigned)t;
                unsigned long long a0, a1, b0, b1;
                bool okA = false, okB = false;
                while (1) {                    // tag-checked burst read
                    if (!okA) {
                        ldcgv2(slot, a0, a1);
                        okA = ((unsigned)(a0 >> 32) == want) & ((unsigned)(a1 >> 32) == want);
                    }
                    if (!okB) {
                        ldcgv2(slot + 2, b0, b1);
                        okB = ((unsigned)(b0 >> 32) == want) & ((unsigned)(b1 >> 32) == want);
                    }
                    if (__all_sync(0xffffffffu, okA & okB)) break;
                }
                unsigned m0 = (unsigned)a0, m1 = (unsigned)a1;
                unsigned m2 = (unsigned)b0, m3 = (unsigned)b1;
                unsigned c0 = __popc(m0), c1 = __popc(m1);
                unsigned c2 = __popc(m2), c3 = __popc(m3);
                unsigned s4 = c0 + c1 + c2 + c3;
                unsigned incl = s4;
                #pragma unroll
                for (int d = 1; d < 32; d <<= 1) {
                    unsigned o = __shfl_up_sync(0xffffffffu, incl, d);
                    if (l >= d) incl += o;
                }
                if (l == 31) sh_total = (int)incl;
                unsigned excl = incl - s4;
                sh_mask[4 * l]     = m0;  sh_off[4 * l]     = (int)excl;
                sh_mask[4 * l + 1] = m1;  sh_off[4 * l + 1] = (int)(excl + c0);
                sh_mask[4 * l + 2] = m2;  sh_off[4 * l + 2] = (int)(excl + c0 + c1);
                sh_mask[4 * l + 3] = m3;  sh_off[4 * l + 3] = (int)(excl + c0 + c1 + c2);
            }
        }
        BAR1(bc);   // S1a

        if (t > 0 && tid < 128) {
            unsigned bits = sh_mask[tid];
            int o = sh_off[tid];
            int base = tid << 5;
            while (bits) {
                int b = __ffs(bits) - 1;
                bits &= bits - 1u;
                sh_idx[o++] = (base + b) << 12;    // row * NN
            }
        }
        BAR1(bc);   // S1b

        {
            const float* wr = w_rec + j0 + (ln8 << 2);
            const int myrow = (wp << 2) + sub;
            float4 acc = gather_rows(wr, sh_idx, sh_total, myrow, nw);
            if (l < 8) part4[wp][ln8] = acc;
        }
        BAR1(bc);   // S2

        if (wp == 0) {
            const float* pf = (const float*)part4;   // row stride 36 floats
            float xr = 0.f;
            #pragma unroll
            for (int w16 = 0; w16 < 16; ++w16) xr += pf[w16 * 36 + l];
            float xt = xr + ((x0 + x1) + (x2 + x3));
            // LIF dynamics, exact reference order
            v *= DECAY;
            float xin = (rt > 0.f) ? 0.f : xt;
            rt -= 1.f;
            v += xin;
            bool sp = (v >= 10.f);
            if (sp) { tl = (float)t / 300.0f; rt = 1.f; v = 0.f; }

            unsigned ball = __ballot_sync(0xffffffffu, sp);
            if (t < TT - 1 && l == 0) {
                stcg64(&g_slot[t][bid],
                       ((unsigned long long)(unsigned)(t + 1) << 32) |
                       (unsigned long long)ball);
                red_release_add(&g_cnt, 1u);
            }
            const int j = j0 + l;
            out[(size_t)t * NN + j]            = sp ? 1.f : 0.f;
            out[(size_t)(TT + t) * NN + j]     = tl;
            out[(size_t)(2 * TT + t) * NN + j] = v;
        }
        // WAR safety unchanged: sh_* for t+1 written after S1a/S1b(t+1); part4
        // rewritten only before S2(t+1); joiners touch only sh_idx (read) and
        // their own part4 rows.
    }
}

// ---------------- launch ----------------
extern "C" void kernel_launch(void* const* d_in, const int* in_sizes, int n_in,
                              void* d_out, int out_size) {
    const int* inp; const float* w; const float* w_rec;
    if (in_sizes[0] == TT * NN) {
        inp = (const int*)d_in[0]; w = (const float*)d_in[1]; w_rec = (const float*)d_in[2];
    } else if (n_in > 1 && in_sizes[1] == TT * NN) {
        inp = (const int*)d_in[1]; w = (const float*)d_in[0]; w_rec = (const float*)d_in[2];
    } else {
        inp = (const int*)d_in[2]; w = (const float*)d_in[0]; w_rec = (const float*)d_in[1];
    }
    float* out = (float*)d_out;

    pack_kernel<<<160, 256>>>(inp);
    lif_kernel<<<NBLK, NT2>>>(w, w_rec, out);
}

// round 17
// speedup vs baseline: 1.0085x; 1.0085x over previous
#include <cuda_runtime.h>

#define NN   4096
#define TT   300
#define TW   10
#define NBLK 128
#define NT2  512
#define TJOIN 96            // step at which xgemm warps join the gather

// ---------------- device scratch ----------------
__device__ unsigned g_mask[NN * TW];
__device__ float    g_Xpart[4ull * 320 * NN];
__device__ __align__(256) unsigned long long g_slot[TT][NBLK];  // {tag=t+1, mask}
__device__ unsigned g_cnt;                                       // cumulative publishes
__device__ unsigned g_wcnt[TW];                                  // per-word tile counters

__device__ __forceinline__ void ldcgv2(const unsigned long long* p,
                                       unsigned long long& a, unsigned long long& b) {
    asm volatile("ld.global.cg.v2.u64 {%0,%1}, [%2];" : "=l"(a), "=l"(b) : "l"(p));
}
__device__ __forceinline__ void stcg64(unsigned long long* p, unsigned long long v) {
    asm volatile("st.global.cg.b64 [%0], %1;" :: "l"(p), "l"(v));
}
__device__ __forceinline__ unsigned ldcg32(const unsigned* p) {
    unsigned v; asm volatile("ld.global.cg.b32 %0, [%1];" : "=r"(v) : "l"(p)); return v;
}
__device__ __forceinline__ unsigned ldacq32(const unsigned* p) {
    unsigned v; asm volatile("ld.acquire.gpu.global.u32 %0, [%1];" : "=r"(v) : "l"(p)); return v;
}
__device__ __forceinline__ void red_release_add(unsigned* p, unsigned v) {
    asm volatile("red.release.gpu.global.add.u32 [%0], %1;" :: "l"(p), "r"(v) : "memory");
}
__device__ __forceinline__ float4 ldnc128(const float* p) {
    float4 v;
    asm volatile("ld.global.nc.v4.f32 {%0,%1,%2,%3}, [%4];"
                 : "=f"(v.x), "=f"(v.y), "=f"(v.z), "=f"(v.w) : "l"(p));
    return v;
}

#define BAR1(cnt)  asm volatile("bar.sync 1, %0;" :: "r"(cnt) : "memory")
#define BAR_GEMM() asm volatile("bar.sync 2, 256;" ::: "memory")

// ---------------- kernel 1: pack inp bits + clear sync state ----------------
__global__ void __launch_bounds__(256) pack_kernel(const int* __restrict__ inp) {
    const int blk  = blockIdx.x;
    const int word = blk % TW;
    const int i    = (blk / TW) * 256 + threadIdx.x;
    unsigned m = 0u;
    const int tb = word * 32;
    #pragma unroll
    for (int b = 0; b < 32; ++b) {
        int t = tb + b;
        if (t < TT) m |= (((unsigned)inp[(size_t)t * NN + i]) & 1u) << b;
    }
    g_mask[i * TW + word] = m;
    int gid = blk * 256 + threadIdx.x;
    if (gid < TT * NBLK) ((unsigned long long*)g_slot)[gid] = 0ull;
    if (gid == 0) g_cnt = 0u;
    if (gid < TW) g_wcnt[gid] = 0u;
}

// ---------------- shared gather routine (nw = 8 or 16 warps) ----------------
__device__ __forceinline__ float4 gather_rows(const float* wr, const int* sh_idx,
                                              int S, int myrow, int nw) {
    float4 acc = make_float4(0.f, 0.f, 0.f, 0.f);
    const int ustr = nw << 2;          // rows per wave
    const int istr = nw << 5;          // rows per 8-wave batch
    for (int base = 0; base < S; base += istr) {
        float4 rv[8];
        #pragma unroll
        for (int u = 0; u < 8; ++u) {
            int kk = base + u * ustr + myrow;
            float4 z = make_float4(0.f, 0.f, 0.f, 0.f);
            if (kk < S) z = ldnc128(wr + sh_idx[kk]);
            rv[u] = z;
        }
        #pragma unroll
        for (int u = 0; u < 8; ++u) {
            acc.x += rv[u].x; acc.y += rv[u].y;
            acc.z += rv[u].z; acc.w += rv[u].w;
        }
    }
    acc.x += __shfl_down_sync(0xffffffffu, acc.x, 16);
    acc.y += __shfl_down_sync(0xffffffffu, acc.y, 16);
    acc.z += __shfl_down_sync(0xffffffffu, acc.z, 16);
    acc.w += __shfl_down_sync(0xffffffffu, acc.w, 16);
    acc.x += __shfl_down_sync(0xffffffffu, acc.x, 8);
    acc.y += __shfl_down_sync(0xffffffffu, acc.y, 8);
    acc.z += __shfl_down_sync(0xffffffffu, acc.z, 8);
    acc.w += __shfl_down_sync(0xffffffffu, acc.w, 8);
    return acc;
}

// ---------------- kernel 2: fused persistent LIF + background X-GEMM ----------
// Warps 0-7: LIF pipeline. Warps 8-15: X-GEMM tiles, then GATED join of the
// gather at t = TJOIN. The smem gate guarantees barrier 1 is used with count
// 256 strictly before t=TJOIN and count 512 strictly from t=TJOIN on — the
// mixed-arrival-count UB that poisoned R16 cannot occur.
__global__ void __launch_bounds__(NT2, 1)
lif_kernel(const float* __restrict__ w, const float* __restrict__ w_rec,
           float* __restrict__ out) {
    __shared__ unsigned long long Adup[128][18];   // xgemm warps only
    __shared__ unsigned sh_mask[128];
    __shared__ int      sh_off[128];
    __shared__ int      sh_total;
    __shared__ int      sh_join;                   // join gate (0 -> 1 at TJOIN)
    __shared__ int      sh_idx[NN];
    __shared__ float4   part4[16][9];

    const int tid = threadIdx.x;
    const int bid = blockIdx.x;
    const int l   = tid & 31;
    const int wp  = tid >> 5;
    const int sub = l >> 3;
    const int ln8 = l & 7;
    const int j0  = bid * 32;

    // ================= warps 8-15: background X-GEMM, then gated join ========
    if (wp >= 8) {
        const int tid2 = tid - 256;
        for (int r = 0; r < 5; ++r) {
            const int tile = bid + (r << 7);       // word-ascending
            const int word = tile >> 6;
            const int s    = tile & 63;
            const int cc   = s >> 2;
            const int q    = s & 3;
            const int j    = cc * 256 + tid2;
            const int ibase = q * 1024;

            unsigned long long acc[16];
            #pragma unroll
            for (int k = 0; k < 16; ++k) acc[k] = 0ull;

            for (int sb = 0; sb < 8; ++sb) {
                int ib = ibase + sb * 128;
                BAR_GEMM();
                for (int e = tid2; e < 2048; e += 256) {
                    int ii = e >> 4, tp = e & 15;
                    unsigned m  = g_mask[(ib + ii) * TW + word];
                    unsigned lo = (m >> (2 * tp))     & 1u ? 0x3f800000u : 0u;
                    unsigned hi = (m >> (2 * tp + 1)) & 1u ? 0x3f800000u : 0u;
                    Adup[ii][tp] = ((unsigned long long)hi << 32) | lo;
                }
                BAR_GEMM();
                for (int ii = 0; ii < 128; ++ii) {
                    unsigned wu = __float_as_uint(w[(size_t)(ib + ii) * NN + j]);
                    unsigned long long wpk;
                    asm("mov.b64 %0, {%1, %1};" : "=l"(wpk) : "r"(wu));
                    const ulonglong2* ap = (const ulonglong2*)(&Adup[ii][0]);
                    #pragma unroll
                    for (int k = 0; k < 8; ++k) {
                        ulonglong2 a2 = ap[k];
                        asm("fma.rn.f32x2 %0, %1, %2, %0;" : "+l"(acc[2*k])   : "l"(wpk), "l"(a2.x));
                        asm("fma.rn.f32x2 %0, %1, %2, %0;" : "+l"(acc[2*k+1]) : "l"(wpk), "l"(a2.y));
                    }
                }
            }
            #pragma unroll
            for (int tp = 0; tp < 16; ++tp) {
                int t0 = word * 32 + 2 * tp;
                g_Xpart[((size_t)q * 320 + t0)     * NN + j] = __uint_as_float((unsigned)acc[tp]);
                g_Xpart[((size_t)q * 320 + t0 + 1) * NN + j] = __uint_as_float((unsigned)(acc[tp] >> 32));
            }
            __threadfence();
            BAR_GEMM();
            if (tid2 == 0) red_release_add(&g_wcnt[word], 1u);
        }
        // ---- GATE: do not touch barrier 1 until LIF warps reach TJOIN ----
        while (*(volatile int*)&sh_join == 0) { __nanosleep(200); }
        // ---- join the gather from t = TJOIN onward (barrier 1 is now 512) ----
        const float* wr = w_rec + j0 + (ln8 << 2);
        const int myrow = (wp << 2) + sub;     // 32..63
        for (int t = TJOIN; t < TT; ++t) {
            BAR1(512);   // S1a
            BAR1(512);   // S1b: sh_idx + sh_total now valid
            float4 acc = gather_rows(wr, sh_idx, sh_total, myrow, 16);
            if (l < 8) part4[wp][ln8] = acc;
            BAR1(512);   // S2
        }
        return;
    }

    // ================= warps 0-7: LIF pipeline ==========
    // zero part4 rows 8-15 (read as exact zeros until the join)
    if (l < 8) part4[wp + 8][ln8] = make_float4(0.f, 0.f, 0.f, 0.f);
    if (tid == 0) { sh_total = 0; *(volatile int*)&sh_join = 0; }
    BAR1(256);

    float v = 0.f, rt = 0.f, tl = 1.f;
    const float DECAY = 0.99004983374916805f;   // fp32(exp(-1/100))

    for (int t = 0; t < TT; ++t) {
        const int bc = (t >= TJOIN) ? 512 : 256;
        const int nw = (t >= TJOIN) ? 16 : 8;
        // open the gate exactly once, BEFORE any 512-count arrival this step
        if (t == TJOIN && wp == 0 && l == 0) *(volatile int*)&sh_join = 1;

        float x0 = 0.f, x1 = 0.f, x2 = 0.f, x3 = 0.f;
        if (wp == 0) {
            if ((t & 31) == 0) {               // wait for this word's Xpart tiles
                if (l == 0) {
                    while (ldacq32(&g_wcnt[t >> 5]) < 64u) {}
                }
                __syncwarp();
            }
            const int j = j0 + l;
            x0 = g_Xpart[(size_t)(0 * 320 + t) * NN + j];
            x1 = g_Xpart[(size_t)(1 * 320 + t) * NN + j];
            x2 = g_Xpart[(size_t)(2 * 320 + t) * NN + j];
            x3 = g_Xpart[(size_t)(3 * 320 + t) * NN + j];
            if (t > 0) {
                if (l == 0) {                  // poll ONE counter word
                    const unsigned want = 128u * (unsigned)t;
                    while (ldcg32(&g_cnt) < want) {}
                }
                __syncwarp();
                const unsigned long long* slot = &g_slot[t - 1][4 * l];
                const unsigned want = (unsigned)t;
                unsigned long long a0, a1, b0, b1;
                bool okA = false, okB = false;
                while (1) {                    // tag-checked burst read
                    if (!okA) {
                        ldcgv2(slot, a0, a1);
                        okA = ((unsigned)(a0 >> 32) == want) & ((unsigned)(a1 >> 32) == want);
                    }
                    if (!okB) {
                        ldcgv2(slot + 2, b0, b1);
                        okB = ((unsigned)(b0 >> 32) == want) & ((unsigned)(b1 >> 32) == want);
                    }
                    if (__all_sync(0xffffffffu, okA & okB)) break;
                }
                unsigned m0 = (unsigned)a0, m1 = (unsigned)a1;
                unsigned m2 = (unsigned)b0, m3 = (unsigned)b1;
                unsigned c0 = __popc(m0), c1 = __popc(m1);
                unsigned c2 = __popc(m2), c3 = __popc(m3);
                unsigned s4 = c0 + c1 + c2 + c3;
                unsigned incl = s4;
                #pragma unroll
                for (int d = 1; d < 32; d <<= 1) {
                    unsigned o = __shfl_up_sync(0xffffffffu, incl, d);
                    if (l >= d) incl += o;
                }
                if (l == 31) sh_total = (int)incl;
                unsigned excl = incl - s4;
                sh_mask[4 * l]     = m0;  sh_off[4 * l]     = (int)excl;
                sh_mask[4 * l + 1] = m1;  sh_off[4 * l + 1] = (int)(excl + c0);
                sh_mask[4 * l + 2] = m2;  sh_off[4 * l + 2] = (int)(excl + c0 + c1);
                sh_mask[4 * l + 3] = m3;  sh_off[4 * l + 3] = (int)(excl + c0 + c1 + c2);
            }
        }
        BAR1(bc);   // S1a

        if (t > 0 && tid < 128) {
            unsigned bits = sh_mask[tid];
            int o = sh_off[tid];
            int base = tid << 5;
            while (bits) {
                int b = __ffs(bits) - 1;
                bits &= bits - 1u;
                sh_idx[o++] = (base + b) << 12;    // row * NN
            }
        }
        BAR1(bc);   // S1b

        {
            const float* wr = w_rec + j0 + (ln8 << 2);
            const int myrow = (wp << 2) + sub;
            float4 acc = gather_rows(wr, sh_idx, sh_total, myrow, nw);
            if (l < 8) part4[wp][ln8] = acc;
        }
        BAR1(bc);   // S2

        if (wp == 0) {
            const float* pf = (const float*)part4;   // row stride 36 floats
            float xr = 0.f;
            #pragma unroll
            for (int w16 = 0; w16 < 16; ++w16) xr += pf[w16 * 36 + l];
            float xt = xr + ((x0 + x1) + (x2 + x3));
            // LIF dynamics, exact reference order
            v *= DECAY;
            float xin = (rt > 0.f) ? 0.f : xt;
            rt -= 1.f;
            v += xin;
            bool sp = (v >= 10.f);
            if (sp) { tl = (float)t / 300.0f; rt = 1.f; v = 0.f; }

            unsigned ball = __ballot_sync(0xffffffffu, sp);
            if (t < TT - 1 && l == 0) {
                stcg64(&g_slot[t][bid],
                       ((unsigned long long)(unsigned)(t + 1) << 32) |
                       (unsigned long long)ball);
                red_release_add(&g_cnt, 1u);
            }
            const int j = j0 + l;
            out[(size_t)t * NN + j]            = sp ? 1.f : 0.f;
            out[(size_t)(TT + t) * NN + j]     = tl;
            out[(size_t)(2 * TT + t) * NN + j] = v;
        }
        // WAR safety unchanged: sh_* for t+1 written after S1a/S1b(t+1); part4
        // rewritten only before S2(t+1); joiners touch only sh_idx (read) and
        // their own part4 rows, strictly inside the 512-count barrier regime.
    }
}

// ---------------- launch ----------------
extern "C" void kernel_launch(void* const* d_in, const int* in_sizes, int n_in,
                              void* d_out, int out_size) {
    const int* inp; const float* w; const float* w_rec;
    if (in_sizes[0] == TT * NN) {
        inp = (const int*)d_in[0]; w = (const float*)d_in[1]; w_rec = (const float*)d_in[2];
    } else if (n_in > 1 && in_sizes[1] == TT * NN) {
        inp = (const int*)d_in[1]; w = (const float*)d_in[0]; w_rec = (const float*)d_in[2];
    } else {
        inp = (const int*)d_in[2]; w = (const float*)d_in[0]; w_rec = (const float*)d_in[1];
    }
    float* out = (float*)d_out;

    pack_kernel<<<160, 256>>>(inp);
    lif_kernel<<<NBLK, NT2>>>(w, w_rec, out);
}